// round 9
// baseline (speedup 1.0000x reference)
#include <cuda_runtime.h>

// PSRoIPool (R-FCN style), fp32.
// features: [B=4, C=490, H=38, W=38], rois: [R=256, 5], out: [R,10,7,7]
// c = (d*P + ph)*P + pw
//
// Numerics (probe-calibrated, round 8: metric is L2, Sum(ref^2)=3.44e4, and
// the 3.0856e-2 base error is ONE window knife-edge incident):
//  - xs/ys/xe/ye exact (integer/16)
//  - bin = roi * RN(1/7)  -- reciprocal MULTIPLY, matching XLA's constant-
//    divisor strength reduction; this is the only remaining rounding step
//    that can flip a ceil() at an exactly-integer bin edge (div-by-7 chain
//    was tested rounds 0-7 and always missed the same incident)
//  - edges via fmaf; two-level (row-then-rows) fp32 summation

#define P_ 7
#define D_ 10
#define H_ 38
#define W_ 38
#define C_ 490
#define R_ 256
#define SCALE_ 0.0625f
#define TOTAL_ (R_ * D_ * P_ * P_)   // 125440

__global__ __launch_bounds__(256) void psroi_kernel(
    const float* __restrict__ feat,
    const float* __restrict__ rois,
    float* __restrict__ out)
{
    int idx = blockIdx.x * blockDim.x + threadIdx.x;
    if (idx >= TOTAL_) return;

    int pw = idx % P_;               // column bin (bin_w, xs)
    int ph = (idx / P_) % P_;        // row bin    (bin_h, ys)
    int d  = (idx / (P_ * P_)) % D_;
    int r  = idx / (P_ * P_ * D_);

    const float* roi = rois + r * 5;
    int   b  = (int)roi[0];
    // jnp.round == round-half-to-even == rintf (RN); *0.0625 is exact
    float xs = __fmul_rn(rintf(roi[1]), SCALE_);
    float ys = __fmul_rn(rintf(roi[2]), SCALE_);
    float xe = __fmul_rn(rintf(__fadd_rn(roi[3], 1.0f)), SCALE_);
    float ye = __fmul_rn(rintf(__fadd_rn(roi[4], 1.0f)), SCALE_);

    const float RECIP7 = 1.0f / 7.0f;   // RN(1/7), constant-folded
    float bin_w = __fmul_rn(fmaxf(__fadd_rn(xe, -xs), 0.1f), RECIP7);
    float bin_h = __fmul_rn(fmaxf(__fadd_rn(ye, -ys), 0.1f), RECIP7);

    // edges: single-rounding FMA; clip to [0,H]/[0,W]
    float hs = floorf(fmaf((float) ph,      bin_h, ys));
    float he = ceilf (fmaf((float)(ph + 1), bin_h, ys));
    float ws = floorf(fmaf((float) pw,      bin_w, xs));
    float we = ceilf (fmaf((float)(pw + 1), bin_w, xs));

    int hstart = (int)fminf(fmaxf(hs, 0.0f), (float)H_);
    int hend   = (int)fminf(fmaxf(he, 0.0f), (float)H_);
    int wstart = (int)fminf(fmaxf(ws, 0.0f), (float)W_);
    int wend   = (int)fminf(fmaxf(we, 0.0f), (float)W_);

    int c = (d * P_ + ph) * P_ + pw;
    const float* fptr = feat + ((size_t)b * C_ + c) * (H_ * W_);

    // two-level accumulation: per-h row sum over w, then sum rows over h
    float sum = 0.0f;
    for (int h = hstart; h < hend; ++h) {
        const float* row = fptr + h * W_;
        float rsum = 0.0f;
        for (int w = wstart; w < wend; ++w) {
            rsum = __fadd_rn(rsum, __ldg(row + w));
        }
        sum = __fadd_rn(sum, rsum);
    }

    int cnt = (hend - hstart) * (wend - wstart);
    out[idx] = (cnt > 0) ? __fdiv_rn(sum, (float)cnt) : 0.0f;
}

extern "C" void kernel_launch(void* const* d_in, const int* in_sizes, int n_in,
                              void* d_out, int out_size)
{
    const float* feat = (const float*)d_in[0];
    const float* rois = (const float*)d_in[1];
    float* out = (float*)d_out;

    const int threads = 256;
    const int blocks = (TOTAL_ + threads - 1) / threads;  // 490
    psroi_kernel<<<blocks, threads>>>(feat, rois, out);
}

// round 10
// speedup vs baseline: 1.0661x; 1.0661x over previous
#include <cuda_runtime.h>

// PSRoIPool (R-FCN style), fp32.
// features: [B=4, C=490, H=38, W=38], rois: [R=256, 5], out: [R,10,7,7]
// c = (d*P + ph)*P + pw
//
// Numerics (locked in round 9, PASS @ rel_err 2.8e-8):
//  - xs/ys/xe/ye exact (integer/16); bin = roi * RN(1/7)  (XLA's
//    reciprocal-multiply strength reduction — NOT fdiv; this was the
//    single knife-edge incident behind the stable 3.0856e-2)
//  - edges via fmaf; row-then-rows fp32 summation order
//
// Perf: windows are provably <= 4x4 (roi width <= 258px -> bin <= 2.304 ->
// span <= 4). Fully unroll a predicated 4x4 gather: 16 independent LDGs
// issue back-to-back (MLP 16) instead of a serial dynamic loop (MLP ~1),
// collapsing ~5 sequential L2-latency exposures into ~1. Adding exact 0.0f
// for predicated-off cells preserves the bit-exact summation order.

#define P_ 7
#define D_ 10
#define H_ 38
#define W_ 38
#define C_ 490
#define R_ 256
#define SCALE_ 0.0625f
#define TOTAL_ (R_ * D_ * P_ * P_)   // 125440

__global__ __launch_bounds__(256) void psroi_kernel(
    const float* __restrict__ feat,
    const float* __restrict__ rois,
    float* __restrict__ out)
{
    int idx = blockIdx.x * blockDim.x + threadIdx.x;
    if (idx >= TOTAL_) return;

    int pw = idx % P_;               // column bin (bin_w, xs)
    int ph = (idx / P_) % P_;        // row bin    (bin_h, ys)
    int d  = (idx / (P_ * P_)) % D_;
    int r  = idx / (P_ * P_ * D_);

    const float* roi = rois + r * 5;
    int   b  = (int)roi[0];
    // jnp.round == round-half-to-even == rintf (RN); *0.0625 is exact
    float xs = __fmul_rn(rintf(roi[1]), SCALE_);
    float ys = __fmul_rn(rintf(roi[2]), SCALE_);
    float xe = __fmul_rn(rintf(__fadd_rn(roi[3], 1.0f)), SCALE_);
    float ye = __fmul_rn(rintf(__fadd_rn(roi[4], 1.0f)), SCALE_);

    const float RECIP7 = 1.0f / 7.0f;   // RN(1/7)
    float bin_w = __fmul_rn(fmaxf(__fadd_rn(xe, -xs), 0.1f), RECIP7);
    float bin_h = __fmul_rn(fmaxf(__fadd_rn(ye, -ys), 0.1f), RECIP7);

    // edges: single-rounding FMA; clip to [0,H]/[0,W]
    float hs = floorf(fmaf((float) ph,      bin_h, ys));
    float he = ceilf (fmaf((float)(ph + 1), bin_h, ys));
    float ws = floorf(fmaf((float) pw,      bin_w, xs));
    float we = ceilf (fmaf((float)(pw + 1), bin_w, xs));

    int hstart = (int)fminf(fmaxf(hs, 0.0f), (float)H_);
    int hend   = (int)fminf(fmaxf(he, 0.0f), (float)H_);
    int wstart = (int)fminf(fmaxf(ws, 0.0f), (float)W_);
    int wend   = (int)fminf(fmaxf(we, 0.0f), (float)W_);

    int c = (d * P_ + ph) * P_ + pw;
    const float* fptr = feat + ((size_t)b * C_ + c) * (H_ * W_)
                             + hstart * W_ + wstart;

    int hspan = hend - hstart;          // 0..4
    int wspan = wend - wstart;          // 0..4

    // predicated 4x4 gather: 16 independent loads, then exact-order reduce
    float v[4][4];
    #pragma unroll
    for (int i = 0; i < 4; ++i) {
        #pragma unroll
        for (int j = 0; j < 4; ++j) {
            bool valid = (i < hspan) && (j < wspan);
            v[i][j] = valid ? __ldg(fptr + i * W_ + j) : 0.0f;
        }
    }

    float sum = 0.0f;
    #pragma unroll
    for (int i = 0; i < 4; ++i) {
        float rsum = 0.0f;
        #pragma unroll
        for (int j = 0; j < 4; ++j)
            rsum = __fadd_rn(rsum, v[i][j]);   // ascending w (zeros exact)
        sum = __fadd_rn(sum, rsum);            // ascending h
    }

    int cnt = hspan * wspan;
    out[idx] = (cnt > 0) ? __fdiv_rn(sum, (float)cnt) : 0.0f;
}

extern "C" void kernel_launch(void* const* d_in, const int* in_sizes, int n_in,
                              void* d_out, int out_size)
{
    const float* feat = (const float*)d_in[0];
    const float* rois = (const float*)d_in[1];
    float* out = (float*)d_out;

    const int threads = 256;
    const int blocks = (TOTAL_ + threads - 1) / threads;  // 490
    psroi_kernel<<<blocks, threads>>>(feat, rois, out);
}

// round 11
// speedup vs baseline: 1.0703x; 1.0039x over previous
#include <cuda_runtime.h>

// PSRoIPool (R-FCN style), fp32.
// features: [B=4, C=490, H=38, W=38], rois: [R=256, 5], out: [R,10,7,7]
// c = (d*P + ph)*P + pw
//
// Numerics (locked, PASS @ rel_err 2.8e-8):
//  - xs/ys/xe/ye exact (integer/16); bin = roi * RN(1/7) (XLA reciprocal-
//    multiply strength reduction, NOT fdiv)
//  - edges via fmaf; summation order ((r0+r1)+r2)+r3, each row ascending w
//
// Perf (R11): occupancy was grid-limited at 39% (26.5 warps/SM). Split each
// output across a LANE PAIR: even lane gathers window rows 0-1, odd lane
// rows 2-3 (window <= 4x4 proven: roi wh <= 256 -> bin <= 2.304 -> span <= 4).
// One shfl moves s01=(r0+r1) to the odd lane which finishes
// ((s01+r2)+r3) — bit-identical grouping. 2x warps -> 2x in-flight loads.

#define P_ 7
#define D_ 10
#define H_ 38
#define W_ 38
#define C_ 490
#define R_ 256
#define SCALE_ 0.0625f
#define TOTAL_ (R_ * D_ * P_ * P_)   // 125440; 2*TOTAL_ = 980 * 256 exactly

__global__ __launch_bounds__(256) void psroi_kernel(
    const float* __restrict__ feat,
    const float* __restrict__ rois,
    float* __restrict__ out)
{
    int t = blockIdx.x * blockDim.x + threadIdx.x;   // 0 .. 2*TOTAL_-1
    int idx  = t >> 1;
    int half = t & 1;                                // 0: rows 0-1, 1: rows 2-3

    int pw = idx % P_;               // column bin (bin_w, xs)
    int ph = (idx / P_) % P_;        // row bin    (bin_h, ys)
    int d  = (idx / (P_ * P_)) % D_;
    int r  = idx / (P_ * P_ * D_);

    const float* roi = rois + r * 5;
    int   b  = (int)roi[0];
    // jnp.round == round-half-to-even == rintf (RN); *0.0625 exact
    float xs = __fmul_rn(rintf(roi[1]), SCALE_);
    float ys = __fmul_rn(rintf(roi[2]), SCALE_);
    float xe = __fmul_rn(rintf(__fadd_rn(roi[3], 1.0f)), SCALE_);
    float ye = __fmul_rn(rintf(__fadd_rn(roi[4], 1.0f)), SCALE_);

    const float RECIP7 = 1.0f / 7.0f;   // RN(1/7)
    float bin_w = __fmul_rn(fmaxf(__fadd_rn(xe, -xs), 0.1f), RECIP7);
    float bin_h = __fmul_rn(fmaxf(__fadd_rn(ye, -ys), 0.1f), RECIP7);

    // edges: single-rounding FMA; clip to [0,H]/[0,W]
    float hs = floorf(fmaf((float) ph,      bin_h, ys));
    float he = ceilf (fmaf((float)(ph + 1), bin_h, ys));
    float ws = floorf(fmaf((float) pw,      bin_w, xs));
    float we = ceilf (fmaf((float)(pw + 1), bin_w, xs));

    int hstart = (int)fminf(fmaxf(hs, 0.0f), (float)H_);
    int hend   = (int)fminf(fmaxf(he, 0.0f), (float)H_);
    int wstart = (int)fminf(fmaxf(ws, 0.0f), (float)W_);
    int wend   = (int)fminf(fmaxf(we, 0.0f), (float)W_);

    int hspan = hend - hstart;          // 0..4
    int wspan = wend - wstart;          // 0..4

    int c = (d * P_ + ph) * P_ + pw;
    const float* rowbase = feat + ((size_t)b * C_ + c) * (H_ * W_)
                                + (hstart + 2 * half) * W_ + wstart;

    // this lane's two window rows (global row indices 2*half, 2*half+1)
    float v[2][4];
    #pragma unroll
    for (int i = 0; i < 2; ++i) {
        int gi = 2 * half + i;
        #pragma unroll
        for (int j = 0; j < 4; ++j) {
            bool valid = (gi < hspan) && (j < wspan);
            v[i][j] = valid ? __ldg(rowbase + i * W_ + j) : 0.0f;
        }
    }

    // row sums, ascending w (predicated-off cells add exact +0.0f)
    float rs0 = __fadd_rn(__fadd_rn(__fadd_rn(v[0][0], v[0][1]), v[0][2]), v[0][3]);
    float rs1 = __fadd_rn(__fadd_rn(__fadd_rn(v[1][0], v[1][1]), v[1][2]), v[1][3]);

    // even lane: s01 = (r0 + r1); ship to odd lane of the pair
    float s01_local = __fadd_rn(rs0, rs1);
    int lane = threadIdx.x & 31;
    float s01 = __shfl_sync(0xffffffffu, s01_local, lane & ~1, 32);

    if (half) {
        // odd lane holds r2 (rs0), r3 (rs1): sum = ((r0+r1)+r2)+r3
        float sum = __fadd_rn(__fadd_rn(s01, rs0), rs1);
        int cnt = hspan * wspan;
        out[idx] = (cnt > 0) ? __fdiv_rn(sum, (float)cnt) : 0.0f;
    }
}

extern "C" void kernel_launch(void* const* d_in, const int* in_sizes, int n_in,
                              void* d_out, int out_size)
{
    const float* feat = (const float*)d_in[0];
    const float* rois = (const float*)d_in[1];
    float* out = (float*)d_out;

    const int threads = 256;
    const int blocks = (2 * TOTAL_) / threads;   // 980, exact
    psroi_kernel<<<blocks, threads>>>(feat, rois, out);
}

// round 12
// speedup vs baseline: 1.2287x; 1.1480x over previous
#include <cuda_runtime.h>

// PSRoIPool (R-FCN style), fp32.
// features: [B=4, C=490, H=38, W=38], rois: [R=256, 5], out: [R,10,7,7]
// c = (d*P + ph)*P + pw
//
// Numerics (locked, PASS @ rel_err 2.845666e-08):
//  - xs/ys/xe/ye exact (integer/16); bin = roi * RN(1/7) (XLA reciprocal-
//    multiply strength reduction, NOT fdiv)
//  - edges via fmaf; two-level ascending summation (rows of w, then h)
//
// Perf (R12): rounds 10/11 were L1tex-WAVEFRONT bound — every gather LDG hit
// 32 distinct planes -> 32 lines -> 32 wavefronts/instr; 2.0M wavefronts
// chip-wide == 7.1-7.7us measured, invariant under occupancy. Fix: one block
// per channel plane c. Stage the 4 batch-planes of c (23.1 KB) into smem
// with coalesced float4 loads (4 wavefronts/instr), then 256 threads (one
// ROI each) gather their <=4x4 windows from smem. Feature bytes read once,
// coalesced; gather moves to LDS.

#define P_ 7
#define D_ 10
#define H_ 38
#define W_ 38
#define C_ 490
#define R_ 256
#define B_ 4
#define PLANE_ (H_ * W_)          // 1444 floats, 5776 B (16B-aligned stride)
#define PLANE4_ (PLANE_ / 4)      // 361 float4
#define SCALE_ 0.0625f

__global__ __launch_bounds__(256) void psroi_kernel(
    const float* __restrict__ feat,
    const float* __restrict__ rois,
    float* __restrict__ out)
{
    __shared__ float sf[B_ * PLANE_];            // 23104 B

    int c   = blockIdx.x;                        // 0..489, channel plane
    int tid = threadIdx.x;                       // 0..255

    // ---- stage feat[b=0..3][c][:,:] into smem, coalesced float4 ----
    const float4* src = (const float4*)feat;     // feat 16B-aligned; plane
    float4*       dst = (float4*)sf;             // stride 361 float4
    #pragma unroll
    for (int k = tid; k < B_ * PLANE4_; k += 256) {
        int b = k / PLANE4_;
        int q = k - b * PLANE4_;
        dst[k] = src[((size_t)b * C_ + c) * PLANE4_ + q];
    }
    __syncthreads();

    // ---- one ROI per thread ----
    int r  = tid;
    int pw = c % P_;                // column bin (bin_w, xs)
    int ph = (c / P_) % P_;         // row bin    (bin_h, ys)

    const float* roi = rois + r * 5;
    int   b  = (int)roi[0];
    // jnp.round == round-half-to-even == rintf (RN); *0.0625 exact
    float xs = __fmul_rn(rintf(roi[1]), SCALE_);
    float ys = __fmul_rn(rintf(roi[2]), SCALE_);
    float xe = __fmul_rn(rintf(__fadd_rn(roi[3], 1.0f)), SCALE_);
    float ye = __fmul_rn(rintf(__fadd_rn(roi[4], 1.0f)), SCALE_);

    const float RECIP7 = 1.0f / 7.0f;   // RN(1/7)
    float bin_w = __fmul_rn(fmaxf(__fadd_rn(xe, -xs), 0.1f), RECIP7);
    float bin_h = __fmul_rn(fmaxf(__fadd_rn(ye, -ys), 0.1f), RECIP7);

    // edges: single-rounding FMA; clip to [0,H]/[0,W]
    float hs = floorf(fmaf((float) ph,      bin_h, ys));
    float he = ceilf (fmaf((float)(ph + 1), bin_h, ys));
    float ws = floorf(fmaf((float) pw,      bin_w, xs));
    float we = ceilf (fmaf((float)(pw + 1), bin_w, xs));

    int hstart = (int)fminf(fmaxf(hs, 0.0f), (float)H_);
    int hend   = (int)fminf(fmaxf(he, 0.0f), (float)H_);
    int wstart = (int)fminf(fmaxf(ws, 0.0f), (float)W_);
    int wend   = (int)fminf(fmaxf(we, 0.0f), (float)W_);

    int hspan = hend - hstart;          // 0..4 (roi wh <= 256 -> span <= 4)
    int wspan = wend - wstart;          // 0..4

    const float* base = sf + b * PLANE_ + hstart * W_ + wstart;

    // predicated 4x4 gather from smem, exact two-level ascending reduce
    float v[4][4];
    #pragma unroll
    for (int i = 0; i < 4; ++i) {
        #pragma unroll
        for (int j = 0; j < 4; ++j) {
            bool valid = (i < hspan) && (j < wspan);
            v[i][j] = valid ? base[i * W_ + j] : 0.0f;
        }
    }

    float sum = 0.0f;
    #pragma unroll
    for (int i = 0; i < 4; ++i) {
        float rsum = 0.0f;
        #pragma unroll
        for (int j = 0; j < 4; ++j)
            rsum = __fadd_rn(rsum, v[i][j]);   // ascending w
        sum = __fadd_rn(sum, rsum);            // ascending h
    }

    int cnt = hspan * wspan;
    // out[r][d][ph][pw] = out[r*490 + c]
    out[r * C_ + c] = (cnt > 0) ? __fdiv_rn(sum, (float)cnt) : 0.0f;
}

extern "C" void kernel_launch(void* const* d_in, const int* in_sizes, int n_in,
                              void* d_out, int out_size)
{
    const float* feat = (const float*)d_in[0];
    const float* rois = (const float*)d_in[1];
    float* out = (float*)d_out;

    psroi_kernel<<<C_, 256>>>(feat, rois, out);   // 490 blocks, 1 ROI/thread
}